// round 16
// baseline (speedup 1.0000x reference)
#include <cuda_runtime.h>
#include <cuda_fp16.h>
#include <cstdint>

#define WIN       16
#define STRIDE    8
#define L_SEQ     8192
#define NUM_WIN   1023
#define WPC       16
#define MROWS     256
#define NT        512

#define PQK       200
#define PVH       104
#define PAH       104
#define PGH       200

#define OFF_QK    0          // s_qk 256*200*2=102400 ; alias s_g (102400) / s_fin fp32 98304
#define OFF_V     102400     // s_v 256*104*2=53248 ; alias s_h half 256*96.. (pitch 104)
#define OFF_A     155648     // s_a 256*104*2=53248
#define SMEM_BYTES 208896

// packed B fragments: uint4 = b-frags for two consecutive k16 steps
// chunk layout: [kp][ntile(12)][lane(32)]; 96-K chunk = 3*12*32 = 1152 uint4
#define PB4_Q     0
#define PB4_O     3456
#define PB4_F1    4608
#define PB4_W2    6912
#define PB4_TOTAL 9216

__device__ __align__(16) uint4 g_pb4[PB4_TOTAL];

__global__ void prep_kernel(const float* __restrict__ qkv_w,
                            const float* __restrict__ out_w,
                            const float* __restrict__ w1,
                            const float* __restrict__ w2,
                            float* __restrict__ out, int out_n) {
    int i = blockIdx.x * blockDim.x + threadIdx.x;
    if (i < out_n) out[i] = 0.0f;
    if (i < PB4_TOTAL) {
        const float* W; int ldn, colbase, rem;
        if (i < PB4_O)       { int ch = i / 1152; rem = i % 1152; W = qkv_w; ldn = 288; colbase = ch * 96; }
        else if (i < PB4_F1) { rem = i - PB4_O; W = out_w; ldn = 96; colbase = 0; }
        else if (i < PB4_W2) { int ch = (i - PB4_F1) / 1152; rem = (i - PB4_F1) % 1152; W = w1; ldn = 192; colbase = ch * 96; }
        else                 { rem = i - PB4_W2; W = w2; ldn = 96; colbase = 0; }
        int kp   = rem / (12 * 32);
        int r2   = rem % (12 * 32);
        int nt   = r2 / 32;
        int lane = r2 % 32;
        int n   = colbase + nt * 8 + (lane >> 2);
        int kb0 = (2 * kp) * 16 + (lane & 3) * 2;
        int kb1 = kb0 + 16;
        __half2 vx = __floats2half2_rn(W[(size_t)kb0 * ldn + n],       W[(size_t)(kb0 + 1) * ldn + n]);
        __half2 vy = __floats2half2_rn(W[(size_t)(kb0 + 8) * ldn + n], W[(size_t)(kb0 + 9) * ldn + n]);
        __half2 vz = __floats2half2_rn(W[(size_t)kb1 * ldn + n],       W[(size_t)(kb1 + 1) * ldn + n]);
        __half2 vw = __floats2half2_rn(W[(size_t)(kb1 + 8) * ldn + n], W[(size_t)(kb1 + 9) * ldn + n]);
        uint4 v;
        v.x = *(uint32_t*)&vx; v.y = *(uint32_t*)&vy;
        v.z = *(uint32_t*)&vz; v.w = *(uint32_t*)&vw;
        g_pb4[i] = v;
    }
}

__device__ __forceinline__ uint32_t smem_u32(const void* p) {
    return (uint32_t)__cvta_generic_to_shared(p);
}
__device__ __forceinline__ void ldsm_x4(uint32_t& r0, uint32_t& r1, uint32_t& r2, uint32_t& r3, uint32_t a) {
    asm volatile("ldmatrix.sync.aligned.m8n8.x4.shared.b16 {%0,%1,%2,%3}, [%4];"
                 : "=r"(r0), "=r"(r1), "=r"(r2), "=r"(r3) : "r"(a));
}
__device__ __forceinline__ void ldsm_x4_t(uint32_t& r0, uint32_t& r1, uint32_t& r2, uint32_t& r3, uint32_t a) {
    asm volatile("ldmatrix.sync.aligned.m8n8.x4.trans.shared.b16 {%0,%1,%2,%3}, [%4];"
                 : "=r"(r0), "=r"(r1), "=r"(r2), "=r"(r3) : "r"(a));
}
__device__ __forceinline__ void mma16816(float c[4], uint32_t a0, uint32_t a1, uint32_t a2, uint32_t a3,
                                         uint32_t b0, uint32_t b1) {
    asm volatile("mma.sync.aligned.m16n8k16.row.col.f32.f16.f16.f32 "
                 "{%0,%1,%2,%3}, {%4,%5,%6,%7}, {%8,%9}, {%0,%1,%2,%3};"
                 : "+f"(c[0]), "+f"(c[1]), "+f"(c[2]), "+f"(c[3])
                 : "r"(a0), "r"(a1), "r"(a2), "r"(a3), "r"(b0), "r"(b1));
}

__device__ __forceinline__ float gelu_tanh(float x) {
    float x3 = x * x * x;
    float inner = 0.7978845608028654f * fmaf(0.044715f, x3, x);
    return 0.5f * x * (1.0f + tanhf(inner));
}
__device__ __forceinline__ int row_pos(int w0, int row) {
    int p = (w0 + (row >> 4)) * STRIDE + (row & 15);
    return p < (L_SEQ - 1) ? p : (L_SEQ - 1);
}

// ---- M=256 GEMM: 16 warps = 4 strips (64 rows) x 4 N-quarters (24 cols) ----
// EPI 1: gelu->half Ch(col c*96)   2: half Hh = seg(gmem)+acc   5: qkv special
template <int NC, int EPI>
__device__ __forceinline__ void gemmM(uint32_t aBase,
                                      const uint4* __restrict__ pb4,
                                      const float* __restrict__ bias,
                                      __half* __restrict__ Ch, int CPh,
                                      __half* __restrict__ Hh,
                                      __half* __restrict__ Cv,
                                      const float* __restrict__ xb, int w0, int tid) {
    const int lane = tid & 31, wid = tid >> 5;
    const int strip = wid & 3;       // 64-row M strip
    const int nq = wid >> 2;         // 24-col N quarter
    const int g = lane >> 2, t = lane & 3;
    const int l15 = lane & 15;
    const int hi8 = (lane >= 16) ? 8 : 0;
    const uint32_t aRow = aBase + (uint32_t)((strip * 64 + l15) * PAH + hi8) * 2;

#pragma unroll
    for (int c = 0; c < NC; c++) {
        float acc[4][3][4];
#pragma unroll
        for (int i = 0; i < 3; i++) {
            float2 bv = *(const float2*)(bias + c * 96 + nq * 24 + i * 8 + t * 2);
#pragma unroll
            for (int rt = 0; rt < 4; rt++) {
                acc[rt][i][0] = bv.x; acc[rt][i][1] = bv.y;
                acc[rt][i][2] = bv.x; acc[rt][i][3] = bv.y;
            }
        }
        const uint4* pw = pb4 + c * 1152 + (nq * 3) * 32 + lane;
#pragma unroll
        for (int kp = 0; kp < 3; kp++) {
            uint4 bv[3];
#pragma unroll
            for (int i = 0; i < 3; i++) bv[i] = __ldg(&pw[(kp * 12 + i) * 32]);
#pragma unroll
            for (int rt = 0; rt < 4; rt++) {
                uint32_t rtOff = aRow + (uint32_t)(rt * 16 * PAH) * 2;
                uint32_t a0, a1, a2, a3;
                ldsm_x4(a0, a1, a2, a3, rtOff + (2 * kp) * 32);
#pragma unroll
                for (int i = 0; i < 3; i++)
                    mma16816(acc[rt][i], a0, a1, a2, a3, bv[i].x, bv[i].y);
                ldsm_x4(a0, a1, a2, a3, rtOff + (2 * kp + 1) * 32);
#pragma unroll
                for (int i = 0; i < 3; i++)
                    mma16816(acc[rt][i], a0, a1, a2, a3, bv[i].z, bv[i].w);
            }
        }
#pragma unroll
        for (int rt = 0; rt < 4; rt++) {
            const int ra = strip * 64 + rt * 16 + g, rb = ra + 8;
#pragma unroll
            for (int i = 0; i < 3; i++) {
                int j = nq * 24 + i * 8 + t * 2;
                if (EPI == 1) {
                    *(__half2*)(Ch + ra * CPh + c * 96 + j) = __floats2half2_rn(gelu_tanh(acc[rt][i][0]), gelu_tanh(acc[rt][i][1]));
                    *(__half2*)(Ch + rb * CPh + c * 96 + j) = __floats2half2_rn(gelu_tanh(acc[rt][i][2]), gelu_tanh(acc[rt][i][3]));
                } else if (EPI == 2) {
                    float2 sa = *(const float2*)(xb + (size_t)row_pos(w0, ra) * 96 + j);
                    float2 sb = *(const float2*)(xb + (size_t)row_pos(w0, rb) * 96 + j);
                    *(__half2*)(Hh + ra * 96 + j) = __floats2half2_rn(sa.x + acc[rt][i][0], sa.y + acc[rt][i][1]);
                    *(__half2*)(Hh + rb * 96 + j) = __floats2half2_rn(sb.x + acc[rt][i][2], sb.y + acc[rt][i][3]);
                } else {  // EPI 5 (qkv)
                    if (c == 0) {
                        *(__half2*)(Ch + ra * CPh + j) = __floats2half2_rn(acc[rt][i][0] * 0.25f, acc[rt][i][1] * 0.25f);
                        *(__half2*)(Ch + rb * CPh + j) = __floats2half2_rn(acc[rt][i][2] * 0.25f, acc[rt][i][3] * 0.25f);
                    } else if (c == 1) {
                        *(__half2*)(Ch + ra * CPh + 96 + j) = __floats2half2_rn(acc[rt][i][0], acc[rt][i][1]);
                        *(__half2*)(Ch + rb * CPh + 96 + j) = __floats2half2_rn(acc[rt][i][2], acc[rt][i][3]);
                    } else {
                        *(__half2*)(Cv + ra * PVH + j) = __floats2half2_rn(acc[rt][i][0], acc[rt][i][1]);
                        *(__half2*)(Cv + rb * PVH + j) = __floats2half2_rn(acc[rt][i][2], acc[rt][i][3]);
                    }
                }
            }
        }
    }
}

// ---- K=192 GEMM (ffn2): Hh(half) += acc ----
__device__ __forceinline__ void gemmW2(uint32_t aBase,
                                       const uint4* __restrict__ pb4,
                                       const float* __restrict__ bias,
                                       __half* __restrict__ Hh, int tid) {
    const int lane = tid & 31, wid = tid >> 5;
    const int strip = wid & 3;
    const int nq = wid >> 2;
    const int g = lane >> 2, t = lane & 3;
    const int l15 = lane & 15;
    const int hi8 = (lane >= 16) ? 8 : 0;
    const uint32_t aRow = aBase + (uint32_t)((strip * 64 + l15) * PGH + hi8) * 2;

    float acc[4][3][4];
#pragma unroll
    for (int i = 0; i < 3; i++) {
        float2 bv = *(const float2*)(bias + nq * 24 + i * 8 + t * 2);
#pragma unroll
        for (int rt = 0; rt < 4; rt++) {
            acc[rt][i][0] = bv.x; acc[rt][i][1] = bv.y;
            acc[rt][i][2] = bv.x; acc[rt][i][3] = bv.y;
        }
    }
    const uint4* pw = pb4 + (nq * 3) * 32 + lane;
#pragma unroll
    for (int kp = 0; kp < 6; kp++) {
        uint4 bv[3];
#pragma unroll
        for (int i = 0; i < 3; i++) bv[i] = __ldg(&pw[(kp * 12 + i) * 32]);
#pragma unroll
        for (int rt = 0; rt < 4; rt++) {
            uint32_t rtOff = aRow + (uint32_t)(rt * 16 * PGH) * 2;
            uint32_t a0, a1, a2, a3;
            ldsm_x4(a0, a1, a2, a3, rtOff + (2 * kp) * 32);
#pragma unroll
            for (int i = 0; i < 3; i++)
                mma16816(acc[rt][i], a0, a1, a2, a3, bv[i].x, bv[i].y);
            ldsm_x4(a0, a1, a2, a3, rtOff + (2 * kp + 1) * 32);
#pragma unroll
            for (int i = 0; i < 3; i++)
                mma16816(acc[rt][i], a0, a1, a2, a3, bv[i].z, bv[i].w);
        }
    }
#pragma unroll
    for (int rt = 0; rt < 4; rt++) {
        const int ra = strip * 64 + rt * 16 + g, rb = ra + 8;
#pragma unroll
        for (int i = 0; i < 3; i++) {
            int j = nq * 24 + i * 8 + t * 2;
            float2 ca = __half22float2(*(__half2*)(Hh + ra * 96 + j));
            float2 cb = __half22float2(*(__half2*)(Hh + rb * 96 + j));
            *(__half2*)(Hh + ra * 96 + j) = __floats2half2_rn(ca.x + acc[rt][i][0], ca.y + acc[rt][i][1]);
            *(__half2*)(Hh + rb * 96 + j) = __floats2half2_rn(cb.x + acc[rt][i][2], cb.y + acc[rt][i][3]);
        }
    }
}

// ---- tensor-core attention: 96 (win,head) pairs over 16 warps, 6 per warp ----
__device__ __forceinline__ void attn_mma(uint32_t uQK, uint32_t uV,
                                         __half* __restrict__ s_a, int tid) {
    const int lane = tid & 31, wid = tid >> 5;
    const int l15 = lane & 15;
    const int lh8 = (lane >= 16) ? 8 : 0;
    const int g = lane >> 2, t = lane & 3;
    const int c0 = 2 * t, c1 = 2 * t + 1, c2 = 2 * t + 8, c3 = 2 * t + 9;

#pragma unroll
    for (int it = 0; it < 6; it++) {
        const int pair = wid + it * 16;      // 0..95
        const int wi = pair / 6, h = pair % 6;
        const int rbase = wi * 16;

        uint32_t qA = uQK + (uint32_t)(((rbase + l15) * PQK + h * 16 + lh8) * 2);
        uint32_t kA = uQK + (uint32_t)(((rbase + l15) * PQK + 96 + h * 16 + lh8) * 2);
        uint32_t vA = uV  + (uint32_t)(((rbase + l15) * PVH + h * 16 + lh8) * 2);

        uint32_t a0, a1, a2, a3, k0, k1, k2, k3, v0, v1, v2, v3;
        ldsm_x4(a0, a1, a2, a3, qA);
        ldsm_x4(k0, k1, k2, k3, kA);
        ldsm_x4_t(v0, v1, v2, v3, vA);

        float s0[4] = {0.f, 0.f, 0.f, 0.f};
        float s1[4] = {0.f, 0.f, 0.f, 0.f};
        mma16816(s0, a0, a1, a2, a3, k0, k2);
        mma16816(s1, a0, a1, a2, a3, k1, k3);

        int g8 = g + 8;
        float e00 = (c0 <= g)  ? __expf(s0[0]) : 0.f;
        float e01 = (c1 <= g)  ? __expf(s0[1]) : 0.f;
        float e02 = (c2 <= g)  ? __expf(s1[0]) : 0.f;
        float e03 = (c3 <= g)  ? __expf(s1[1]) : 0.f;
        float e10 = (c0 <= g8) ? __expf(s0[2]) : 0.f;
        float e11 = (c1 <= g8) ? __expf(s0[3]) : 0.f;
        float e12 = (c2 <= g8) ? __expf(s1[2]) : 0.f;
        float e13 = (c3 <= g8) ? __expf(s1[3]) : 0.f;

        float d0 = e00 + e01 + e02 + e03;
        float d1 = e10 + e11 + e12 + e13;
        d0 += __shfl_xor_sync(0xffffffffu, d0, 1);
        d0 += __shfl_xor_sync(0xffffffffu, d0, 2);
        d1 += __shfl_xor_sync(0xffffffffu, d1, 1);
        d1 += __shfl_xor_sync(0xffffffffu, d1, 2);
        float i0 = 1.0f / d0, i1 = 1.0f / d1;

        __half2 p0 = __floats2half2_rn(e00 * i0, e01 * i0);
        __half2 p1 = __floats2half2_rn(e10 * i1, e11 * i1);
        __half2 p2 = __floats2half2_rn(e02 * i0, e03 * i0);
        __half2 p3 = __floats2half2_rn(e12 * i1, e13 * i1);
        uint32_t pa0 = *(uint32_t*)&p0, pa1 = *(uint32_t*)&p1;
        uint32_t pa2 = *(uint32_t*)&p2, pa3 = *(uint32_t*)&p3;

        float o0[4] = {0.f, 0.f, 0.f, 0.f};
        float o1[4] = {0.f, 0.f, 0.f, 0.f};
        mma16816(o0, pa0, pa1, pa2, pa3, v0, v1);
        mma16816(o1, pa0, pa1, pa2, pa3, v2, v3);

        __half* ba = s_a + (rbase + g) * PAH + h * 16;
        __half* bb = s_a + (rbase + g8) * PAH + h * 16;
        *(__half2*)(ba + 2 * t)     = __floats2half2_rn(o0[0], o0[1]);
        *(__half2*)(ba + 8 + 2 * t) = __floats2half2_rn(o1[0], o1[1]);
        *(__half2*)(bb + 2 * t)     = __floats2half2_rn(o0[2], o0[3]);
        *(__half2*)(bb + 8 + 2 * t) = __floats2half2_rn(o1[2], o1[3]);
    }
}

// ---- LayerNorm 256x96, 2 threads/row (512 threads) ----
// OUT 0: half->dst_h(PAH)  1: fp32->dst_f(96).  SRC 0: half smem (96)  1: gmem fp32 rows
template <int OUT, int SRC>
__device__ __forceinline__ void ln256(const __half* __restrict__ srcH, const float* __restrict__ xb, int w0,
                                      __half* __restrict__ dst_h, float* __restrict__ dst_f,
                                      const float* __restrict__ gg, const float* __restrict__ bb, int tid) {
    int row = tid >> 1, hf = tid & 1;
    float v[48];
    if (SRC == 1) {
        const float* rp = xb + (size_t)row_pos(w0, row) * 96 + hf * 48;
#pragma unroll
        for (int i = 0; i < 12; i++) {
            float4 f = *(const float4*)(rp + i * 4);
            v[4*i] = f.x; v[4*i+1] = f.y; v[4*i+2] = f.z; v[4*i+3] = f.w;
        }
    } else {
        const __half2* rp = (const __half2*)(srcH + row * 96 + hf * 48);
#pragma unroll
        for (int i = 0; i < 24; i++) {
            float2 f = __half22float2(rp[i]);
            v[2*i] = f.x; v[2*i+1] = f.y;
        }
    }
    float s = 0.f;
#pragma unroll
    for (int i = 0; i < 48; i++) s += v[i];
    s += __shfl_xor_sync(0xffffffffu, s, 1);
    float mean = s * (1.0f / 96.0f);
    float q = 0.f;
#pragma unroll
    for (int i = 0; i < 48; i++) { float d = v[i] - mean; q = fmaf(d, d, q); }
    q += __shfl_xor_sync(0xffffffffu, q, 1);
    float rstd = rsqrtf(q * (1.0f / 96.0f) + 1e-5f);
#pragma unroll
    for (int i = 0; i < 24; i++) {
        int d = hf * 48 + i * 2;
        float2 gv = *(const float2*)(gg + d);
        float2 bv = *(const float2*)(bb + d);
        float ox = (v[2*i]   - mean) * rstd * gv.x + bv.x;
        float oy = (v[2*i+1] - mean) * rstd * gv.y + bv.y;
        if (OUT == 0) {
            *(__half2*)(dst_h + row * PAH + d) = __floats2half2_rn(ox, oy);
        } else {
            *(float2*)(dst_f + row * 96 + d) = make_float2(ox, oy);
        }
    }
}

__global__ void __launch_bounds__(NT, 1)
win_block_kernel(const float* __restrict__ x,
                 const float* __restrict__ ln1_g, const float* __restrict__ ln1_b,
                 const float* __restrict__ qkv_b,
                 const float* __restrict__ out_b,
                 const float* __restrict__ ln2_g, const float* __restrict__ ln2_b,
                 const float* __restrict__ ffn_b1, const float* __restrict__ ffn_b2,
                 const float* __restrict__ pln_g, const float* __restrict__ pln_b,
                 float* __restrict__ out) {
    extern __shared__ char sm[];
    __half* s_qk  = (__half*)(sm + OFF_QK);   // 256 x 200 (Q|K)
    __half* s_v   = (__half*)(sm + OFF_V);    // 256 x 104 (V row-major)
    __half* s_a   = (__half*)(sm + OFF_A);    // 256 x 104
    __half* s_g   = (__half*)(sm + OFF_QK);   // alias (gelu out 256x200)
    float*  s_fin = (float*)(sm + OFF_QK);    // alias (final LN fp32 256x96)
    __half* s_h   = (__half*)(sm + OFF_V);    // alias (residual half 256x96)

    const uint32_t uQK = smem_u32(s_qk);
    const uint32_t uV  = smem_u32(s_v);
    const uint32_t uA  = smem_u32(s_a);
    const uint32_t uG  = smem_u32(s_g);

    const int tid = threadIdx.x;
    const int w0  = blockIdx.x * WPC;
    const int b   = blockIdx.y;
    const float* xb = x + (size_t)b * L_SEQ * 96;

    ln256<0, 1>(nullptr, xb, w0, s_a, nullptr, ln1_g, ln1_b, tid);
    __syncthreads();

    gemmM<3, 5>(uA, g_pb4 + PB4_Q, qkv_b, s_qk, PQK, nullptr, s_v, xb, w0, tid);
    __syncthreads();

    attn_mma(uQK, uV, s_a, tid);
    __syncthreads();

    gemmM<1, 2>(uA, g_pb4 + PB4_O, out_b, nullptr, 0, s_h, nullptr, xb, w0, tid);
    __syncthreads();

    ln256<0, 0>(s_h, nullptr, 0, s_a, nullptr, ln2_g, ln2_b, tid);
    __syncthreads();

    gemmM<2, 1>(uA, g_pb4 + PB4_F1, ffn_b1, s_g, PGH, nullptr, nullptr, xb, w0, tid);
    __syncthreads();

    gemmW2(uG, g_pb4 + PB4_W2, ffn_b2, s_h, tid);
    __syncthreads();

    ln256<1, 0>(s_h, nullptr, 0, nullptr, s_fin, pln_g, pln_b, tid);
    __syncthreads();

    int nw = NUM_WIN - w0; if (nw > WPC) nw = WPC;
    const int LP = nw * 8 + 8;
    for (int i = tid; i < LP * 96; i += NT) {
        int lp = i / 96, d = i - lp * 96;
        int pos = w0 * STRIDE + lp;
        size_t oidx = ((size_t)b * L_SEQ + pos) * 96 + d;
        if (lp >= 8 && lp < nw * 8) {
            int wiH = lp >> 3, r = lp & 7;
            float vH = s_fin[(wiH * 16 + r) * 96 + d];
            float vL = s_fin[((wiH - 1) * 16 + r + 8) * 96 + d];
            out[oidx] = (vH + vL) * 0.5f;
        } else if (lp < 8) {
            float invc = (pos < STRIDE) ? 1.0f : 0.5f;
            atomicAdd(out + oidx, s_fin[lp * 96 + d] * invc);
        } else {
            int r = lp - (nw - 1) * 8;
            float invc = (pos >= L_SEQ - STRIDE) ? 1.0f : 0.5f;
            atomicAdd(out + oidx, s_fin[((nw - 1) * 16 + r) * 96 + d] * invc);
        }
    }
}

extern "C" void kernel_launch(void* const* d_in, const int* in_sizes, int n_in,
                              void* d_out, int out_size) {
    const float* x      = (const float*)d_in[0];
    const float* ln1_g  = (const float*)d_in[1];
    const float* ln1_b  = (const float*)d_in[2];
    const float* qkv_w  = (const float*)d_in[3];
    const float* qkv_b  = (const float*)d_in[4];
    const float* out_w  = (const float*)d_in[5];
    const float* out_b  = (const float*)d_in[6];
    const float* ln2_g  = (const float*)d_in[7];
    const float* ln2_b  = (const float*)d_in[8];
    const float* ffn_w1 = (const float*)d_in[9];
    const float* ffn_b1 = (const float*)d_in[10];
    const float* ffn_w2 = (const float*)d_in[11];
    const float* ffn_b2 = (const float*)d_in[12];
    const float* pln_g  = (const float*)d_in[13];
    const float* pln_b  = (const float*)d_in[14];
    float* out = (float*)d_out;

    const int B = in_sizes[0] / (L_SEQ * 96);
    const int nblk = (NUM_WIN + WPC - 1) / WPC;   // 64

    static int attr_set = 0;
    if (!attr_set) {
        cudaFuncSetAttribute(win_block_kernel,
                             cudaFuncAttributeMaxDynamicSharedMemorySize, SMEM_BYTES);
        attr_set = 1;
    }

    prep_kernel<<<(out_size + 255) / 256, 256>>>(qkv_w, out_w, ffn_w1, ffn_w2, out, out_size);

    dim3 grid(nblk, B);
    win_block_kernel<<<grid, NT, SMEM_BYTES>>>(
        x, ln1_g, ln1_b, qkv_b, out_b, ln2_g, ln2_b,
        ffn_b1, ffn_b2, pln_g, pln_b, out);
}

// round 17
// speedup vs baseline: 1.1709x; 1.1709x over previous
#include <cuda_runtime.h>
#include <cuda_fp16.h>
#include <cstdint>

#define WIN       16
#define STRIDE    8
#define L_SEQ     8192
#define NUM_WIN   1023
#define WPC       8
#define MROWS     128
#define NT        512

#define PQK       200
#define PVH       104
#define PAH       104
#define PGH       200

#define OFF_QK    0
#define OFF_V     51200
#define OFF_A     77824
#define SMEM_BYTES 104448

// packed B fragments: uint4 = b-frags for two consecutive k16 steps
// chunk layout: [kp][ntile(12)][lane(32)]; 96-K chunk = 3*12*32 = 1152 uint4
#define PB4_Q     0
#define PB4_O     3456
#define PB4_F1    4608
#define PB4_W2    6912
#define PB4_TOTAL 9216

__device__ __align__(16) uint4 g_pb4[PB4_TOTAL];

__global__ void prep_kernel(const float* __restrict__ qkv_w,
                            const float* __restrict__ out_w,
                            const float* __restrict__ w1,
                            const float* __restrict__ w2,
                            float* __restrict__ out, int out_n) {
    int i = blockIdx.x * blockDim.x + threadIdx.x;
    // selective zero: only atomic-target positions (CTA boundaries + global tail)
    if (i < out_n) {
        int pos = (i / 96) & (L_SEQ - 1);
        if ((pos & 63) < 8 || pos >= L_SEQ - 8) out[i] = 0.0f;
    }
    if (i < PB4_TOTAL) {
        const float* W; int ldn, colbase, rem;
        if (i < PB4_O)       { int ch = i / 1152; rem = i % 1152; W = qkv_w; ldn = 288; colbase = ch * 96; }
        else if (i < PB4_F1) { rem = i - PB4_O; W = out_w; ldn = 96; colbase = 0; }
        else if (i < PB4_W2) { int ch = (i - PB4_F1) / 1152; rem = (i - PB4_F1) % 1152; W = w1; ldn = 192; colbase = ch * 96; }
        else                 { rem = i - PB4_W2; W = w2; ldn = 96; colbase = 0; }
        int kp   = rem / (12 * 32);
        int r2   = rem % (12 * 32);
        int nt   = r2 / 32;
        int lane = r2 % 32;
        int n   = colbase + nt * 8 + (lane >> 2);
        int kb0 = (2 * kp) * 16 + (lane & 3) * 2;
        int kb1 = kb0 + 16;
        __half2 vx = __floats2half2_rn(W[(size_t)kb0 * ldn + n],       W[(size_t)(kb0 + 1) * ldn + n]);
        __half2 vy = __floats2half2_rn(W[(size_t)(kb0 + 8) * ldn + n], W[(size_t)(kb0 + 9) * ldn + n]);
        __half2 vz = __floats2half2_rn(W[(size_t)kb1 * ldn + n],       W[(size_t)(kb1 + 1) * ldn + n]);
        __half2 vw = __floats2half2_rn(W[(size_t)(kb1 + 8) * ldn + n], W[(size_t)(kb1 + 9) * ldn + n]);
        uint4 v;
        v.x = *(uint32_t*)&vx; v.y = *(uint32_t*)&vy;
        v.z = *(uint32_t*)&vz; v.w = *(uint32_t*)&vw;
        g_pb4[i] = v;
    }
}

__device__ __forceinline__ uint32_t smem_u32(const void* p) {
    return (uint32_t)__cvta_generic_to_shared(p);
}
__device__ __forceinline__ void ldsm_x4(uint32_t& r0, uint32_t& r1, uint32_t& r2, uint32_t& r3, uint32_t a) {
    asm volatile("ldmatrix.sync.aligned.m8n8.x4.shared.b16 {%0,%1,%2,%3}, [%4];"
                 : "=r"(r0), "=r"(r1), "=r"(r2), "=r"(r3) : "r"(a));
}
__device__ __forceinline__ void ldsm_x4_t(uint32_t& r0, uint32_t& r1, uint32_t& r2, uint32_t& r3, uint32_t a) {
    asm volatile("ldmatrix.sync.aligned.m8n8.x4.trans.shared.b16 {%0,%1,%2,%3}, [%4];"
                 : "=r"(r0), "=r"(r1), "=r"(r2), "=r"(r3) : "r"(a));
}
__device__ __forceinline__ void mma16816(float c[4], uint32_t a0, uint32_t a1, uint32_t a2, uint32_t a3,
                                         uint32_t b0, uint32_t b1) {
    asm volatile("mma.sync.aligned.m16n8k16.row.col.f32.f16.f16.f32 "
                 "{%0,%1,%2,%3}, {%4,%5,%6,%7}, {%8,%9}, {%0,%1,%2,%3};"
                 : "+f"(c[0]), "+f"(c[1]), "+f"(c[2]), "+f"(c[3])
                 : "r"(a0), "r"(a1), "r"(a2), "r"(a3), "r"(b0), "r"(b1));
}

__device__ __forceinline__ float gelu_tanh(float x) {
    float x3 = x * x * x;
    float inner = 0.7978845608028654f * fmaf(0.044715f, x3, x);
    return 0.5f * x * (1.0f + tanhf(inner));
}
__device__ __forceinline__ int row_pos(int w0, int row) {
    int p = (w0 + (row >> 4)) * STRIDE + (row & 15);
    return p < (L_SEQ - 1) ? p : (L_SEQ - 1);
}

// ---- M=128 GEMM: 16 warps = 4 strips (32 rows) x 4 N-quarters (24 cols) ----
// Flattened (chunk, kp) steps with B double-buffer prefetch.
// EPI 1: gelu->half Ch(col c*96)   2: half Hh = seg(gmem)+acc   5: qkv special
template <int NC, int EPI>
__device__ __forceinline__ void gemmM(uint32_t aBase,
                                      const uint4* __restrict__ pb4,
                                      const float* __restrict__ bias,
                                      __half* __restrict__ Ch, int CPh,
                                      __half* __restrict__ Hh,
                                      __half* __restrict__ Cv,
                                      const float* __restrict__ xb, int w0, int tid) {
    const int lane = tid & 31, wid = tid >> 5;
    const int strip = wid & 3;       // 32-row M strip
    const int nq = wid >> 2;         // 24-col N quarter
    const int g = lane >> 2, t = lane & 3;
    const int l15 = lane & 15;
    const int hi8 = (lane >= 16) ? 8 : 0;
    const uint32_t aRow = aBase + (uint32_t)((strip * 32 + l15) * PAH + hi8) * 2;
    const uint4* pwBase = pb4 + (nq * 3) * 32 + lane;

    uint4 bv[3];
#pragma unroll
    for (int i = 0; i < 3; i++) bv[i] = __ldg(&pwBase[i * 32]);

    float acc[2][3][4];
#pragma unroll
    for (int s = 0; s < NC * 3; s++) {
        const int c = s / 3, kp = s % 3;
        if (kp == 0) {
#pragma unroll
            for (int i = 0; i < 3; i++) {
                float2 bb = *(const float2*)(bias + c * 96 + nq * 24 + i * 8 + t * 2);
#pragma unroll
                for (int rt = 0; rt < 2; rt++) {
                    acc[rt][i][0] = bb.x; acc[rt][i][1] = bb.y;
                    acc[rt][i][2] = bb.x; acc[rt][i][3] = bb.y;
                }
            }
        }
        uint4 bnext[3];
        if (s + 1 < NC * 3) {
            const uint4* pn = pwBase + ((s + 1) / 3) * 1152 + ((s + 1) % 3) * 12 * 32;
#pragma unroll
            for (int i = 0; i < 3; i++) bnext[i] = __ldg(&pn[i * 32]);
        }
#pragma unroll
        for (int rt = 0; rt < 2; rt++) {
            uint32_t rtOff = aRow + (uint32_t)(rt * 16 * PAH) * 2;
            uint32_t a0, a1, a2, a3;
            ldsm_x4(a0, a1, a2, a3, rtOff + (2 * kp) * 32);
#pragma unroll
            for (int i = 0; i < 3; i++)
                mma16816(acc[rt][i], a0, a1, a2, a3, bv[i].x, bv[i].y);
            ldsm_x4(a0, a1, a2, a3, rtOff + (2 * kp + 1) * 32);
#pragma unroll
            for (int i = 0; i < 3; i++)
                mma16816(acc[rt][i], a0, a1, a2, a3, bv[i].z, bv[i].w);
        }
        if (s + 1 < NC * 3) {
#pragma unroll
            for (int i = 0; i < 3; i++) bv[i] = bnext[i];
        }
        if (kp == 2) {
#pragma unroll
            for (int rt = 0; rt < 2; rt++) {
                const int ra = strip * 32 + rt * 16 + g, rb = ra + 8;
#pragma unroll
                for (int i = 0; i < 3; i++) {
                    int j = nq * 24 + i * 8 + t * 2;
                    if (EPI == 1) {
                        *(__half2*)(Ch + ra * CPh + c * 96 + j) = __floats2half2_rn(gelu_tanh(acc[rt][i][0]), gelu_tanh(acc[rt][i][1]));
                        *(__half2*)(Ch + rb * CPh + c * 96 + j) = __floats2half2_rn(gelu_tanh(acc[rt][i][2]), gelu_tanh(acc[rt][i][3]));
                    } else if (EPI == 2) {
                        float2 sa = *(const float2*)(xb + (size_t)row_pos(w0, ra) * 96 + j);
                        float2 sb = *(const float2*)(xb + (size_t)row_pos(w0, rb) * 96 + j);
                        *(__half2*)(Hh + ra * 96 + j) = __floats2half2_rn(sa.x + acc[rt][i][0], sa.y + acc[rt][i][1]);
                        *(__half2*)(Hh + rb * 96 + j) = __floats2half2_rn(sb.x + acc[rt][i][2], sb.y + acc[rt][i][3]);
                    } else {  // EPI 5 (qkv)
                        if (c == 0) {
                            *(__half2*)(Ch + ra * CPh + j) = __floats2half2_rn(acc[rt][i][0] * 0.25f, acc[rt][i][1] * 0.25f);
                            *(__half2*)(Ch + rb * CPh + j) = __floats2half2_rn(acc[rt][i][2] * 0.25f, acc[rt][i][3] * 0.25f);
                        } else if (c == 1) {
                            *(__half2*)(Ch + ra * CPh + 96 + j) = __floats2half2_rn(acc[rt][i][0], acc[rt][i][1]);
                            *(__half2*)(Ch + rb * CPh + 96 + j) = __floats2half2_rn(acc[rt][i][2], acc[rt][i][3]);
                        } else {
                            *(__half2*)(Cv + ra * PVH + j) = __floats2half2_rn(acc[rt][i][0], acc[rt][i][1]);
                            *(__half2*)(Cv + rb * PVH + j) = __floats2half2_rn(acc[rt][i][2], acc[rt][i][3]);
                        }
                    }
                }
            }
        }
    }
}

// ---- K=192 GEMM (ffn2): Hh(half) += acc, with B prefetch ----
__device__ __forceinline__ void gemmW2(uint32_t aBase,
                                       const uint4* __restrict__ pb4,
                                       const float* __restrict__ bias,
                                       __half* __restrict__ Hh, int tid) {
    const int lane = tid & 31, wid = tid >> 5;
    const int strip = wid & 3;
    const int nq = wid >> 2;
    const int g = lane >> 2, t = lane & 3;
    const int l15 = lane & 15;
    const int hi8 = (lane >= 16) ? 8 : 0;
    const uint32_t aRow = aBase + (uint32_t)((strip * 32 + l15) * PGH + hi8) * 2;
    const uint4* pw = pb4 + (nq * 3) * 32 + lane;

    float acc[2][3][4];
#pragma unroll
    for (int i = 0; i < 3; i++) {
        float2 bv2 = *(const float2*)(bias + nq * 24 + i * 8 + t * 2);
#pragma unroll
        for (int rt = 0; rt < 2; rt++) {
            acc[rt][i][0] = bv2.x; acc[rt][i][1] = bv2.y;
            acc[rt][i][2] = bv2.x; acc[rt][i][3] = bv2.y;
        }
    }
    uint4 bv[3];
#pragma unroll
    for (int i = 0; i < 3; i++) bv[i] = __ldg(&pw[i * 32]);
#pragma unroll
    for (int kp = 0; kp < 6; kp++) {
        uint4 bnext[3];
        if (kp + 1 < 6) {
#pragma unroll
            for (int i = 0; i < 3; i++) bnext[i] = __ldg(&pw[((kp + 1) * 12 + i) * 32]);
        }
#pragma unroll
        for (int rt = 0; rt < 2; rt++) {
            uint32_t rtOff = aRow + (uint32_t)(rt * 16 * PGH) * 2;
            uint32_t a0, a1, a2, a3;
            ldsm_x4(a0, a1, a2, a3, rtOff + (2 * kp) * 32);
#pragma unroll
            for (int i = 0; i < 3; i++)
                mma16816(acc[rt][i], a0, a1, a2, a3, bv[i].x, bv[i].y);
            ldsm_x4(a0, a1, a2, a3, rtOff + (2 * kp + 1) * 32);
#pragma unroll
            for (int i = 0; i < 3; i++)
                mma16816(acc[rt][i], a0, a1, a2, a3, bv[i].z, bv[i].w);
        }
        if (kp + 1 < 6) {
#pragma unroll
            for (int i = 0; i < 3; i++) bv[i] = bnext[i];
        }
    }
#pragma unroll
    for (int rt = 0; rt < 2; rt++) {
        const int ra = strip * 32 + rt * 16 + g, rb = ra + 8;
#pragma unroll
        for (int i = 0; i < 3; i++) {
            int j = nq * 24 + i * 8 + t * 2;
            float2 ca = __half22float2(*(__half2*)(Hh + ra * 96 + j));
            float2 cb = __half22float2(*(__half2*)(Hh + rb * 96 + j));
            *(__half2*)(Hh + ra * 96 + j) = __floats2half2_rn(ca.x + acc[rt][i][0], ca.y + acc[rt][i][1]);
            *(__half2*)(Hh + rb * 96 + j) = __floats2half2_rn(cb.x + acc[rt][i][2], cb.y + acc[rt][i][3]);
        }
    }
}

// ---- tensor-core attention: 48 (win,head) pairs over 16 warps, 3 per warp ----
__device__ __forceinline__ void attn_mma(uint32_t uQK, uint32_t uV,
                                         __half* __restrict__ s_a, int tid) {
    const int lane = tid & 31, wid = tid >> 5;
    const int l15 = lane & 15;
    const int lh8 = (lane >= 16) ? 8 : 0;
    const int g = lane >> 2, t = lane & 3;
    const int c0 = 2 * t, c1 = 2 * t + 1, c2 = 2 * t + 8, c3 = 2 * t + 9;

#pragma unroll
    for (int it = 0; it < 3; it++) {
        const int pair = wid + it * 16;      // 0..47
        const int wi = pair / 6, h = pair % 6;
        const int rbase = wi * 16;

        uint32_t qA = uQK + (uint32_t)(((rbase + l15) * PQK + h * 16 + lh8) * 2);
        uint32_t kA = uQK + (uint32_t)(((rbase + l15) * PQK + 96 + h * 16 + lh8) * 2);
        uint32_t vA = uV  + (uint32_t)(((rbase + l15) * PVH + h * 16 + lh8) * 2);

        uint32_t a0, a1, a2, a3, k0, k1, k2, k3, v0, v1, v2, v3;
        ldsm_x4(a0, a1, a2, a3, qA);
        ldsm_x4(k0, k1, k2, k3, kA);
        ldsm_x4_t(v0, v1, v2, v3, vA);

        float s0[4] = {0.f, 0.f, 0.f, 0.f};
        float s1[4] = {0.f, 0.f, 0.f, 0.f};
        mma16816(s0, a0, a1, a2, a3, k0, k2);
        mma16816(s1, a0, a1, a2, a3, k1, k3);

        int g8 = g + 8;
        float e00 = (c0 <= g)  ? __expf(s0[0]) : 0.f;
        float e01 = (c1 <= g)  ? __expf(s0[1]) : 0.f;
        float e02 = (c2 <= g)  ? __expf(s1[0]) : 0.f;
        float e03 = (c3 <= g)  ? __expf(s1[1]) : 0.f;
        float e10 = (c0 <= g8) ? __expf(s0[2]) : 0.f;
        float e11 = (c1 <= g8) ? __expf(s0[3]) : 0.f;
        float e12 = (c2 <= g8) ? __expf(s1[2]) : 0.f;
        float e13 = (c3 <= g8) ? __expf(s1[3]) : 0.f;

        float d0 = e00 + e01 + e02 + e03;
        float d1 = e10 + e11 + e12 + e13;
        d0 += __shfl_xor_sync(0xffffffffu, d0, 1);
        d0 += __shfl_xor_sync(0xffffffffu, d0, 2);
        d1 += __shfl_xor_sync(0xffffffffu, d1, 1);
        d1 += __shfl_xor_sync(0xffffffffu, d1, 2);
        float i0 = 1.0f / d0, i1 = 1.0f / d1;

        __half2 p0 = __floats2half2_rn(e00 * i0, e01 * i0);
        __half2 p1 = __floats2half2_rn(e10 * i1, e11 * i1);
        __half2 p2 = __floats2half2_rn(e02 * i0, e03 * i0);
        __half2 p3 = __floats2half2_rn(e12 * i1, e13 * i1);
        uint32_t pa0 = *(uint32_t*)&p0, pa1 = *(uint32_t*)&p1;
        uint32_t pa2 = *(uint32_t*)&p2, pa3 = *(uint32_t*)&p3;

        float o0[4] = {0.f, 0.f, 0.f, 0.f};
        float o1[4] = {0.f, 0.f, 0.f, 0.f};
        mma16816(o0, pa0, pa1, pa2, pa3, v0, v1);
        mma16816(o1, pa0, pa1, pa2, pa3, v2, v3);

        __half* ba = s_a + (rbase + g) * PAH + h * 16;
        __half* bb = s_a + (rbase + g8) * PAH + h * 16;
        *(__half2*)(ba + 2 * t)     = __floats2half2_rn(o0[0], o0[1]);
        *(__half2*)(ba + 8 + 2 * t) = __floats2half2_rn(o1[0], o1[1]);
        *(__half2*)(bb + 2 * t)     = __floats2half2_rn(o0[2], o0[3]);
        *(__half2*)(bb + 8 + 2 * t) = __floats2half2_rn(o1[2], o1[3]);
    }
}

// ---- LayerNorm 128x96, 4 threads/row ----
template <int OUT, int SRC>
__device__ __forceinline__ void ln128(const __half* __restrict__ srcH, const float* __restrict__ xb, int w0,
                                      __half* __restrict__ dst_h, float* __restrict__ dst_f,
                                      const float* __restrict__ gg, const float* __restrict__ bb, int tid) {
    int row = tid >> 2, qt = tid & 3;
    float v[24];
    if (SRC == 1) {
        const float* rp = xb + (size_t)row_pos(w0, row) * 96 + qt * 24;
#pragma unroll
        for (int i = 0; i < 6; i++) {
            float4 f = *(const float4*)(rp + i * 4);
            v[4*i] = f.x; v[4*i+1] = f.y; v[4*i+2] = f.z; v[4*i+3] = f.w;
        }
    } else {
        const __half2* rp = (const __half2*)(srcH + row * 96 + qt * 24);
#pragma unroll
        for (int i = 0; i < 12; i++) {
            float2 f = __half22float2(rp[i]);
            v[2*i] = f.x; v[2*i+1] = f.y;
        }
    }
    float s = 0.f;
#pragma unroll
    for (int i = 0; i < 24; i++) s += v[i];
    s += __shfl_xor_sync(0xffffffffu, s, 1);
    s += __shfl_xor_sync(0xffffffffu, s, 2);
    float mean = s * (1.0f / 96.0f);
    float q = 0.f;
#pragma unroll
    for (int i = 0; i < 24; i++) { float d = v[i] - mean; q = fmaf(d, d, q); }
    q += __shfl_xor_sync(0xffffffffu, q, 1);
    q += __shfl_xor_sync(0xffffffffu, q, 2);
    float rstd = rsqrtf(q * (1.0f / 96.0f) + 1e-5f);
#pragma unroll
    for (int i = 0; i < 12; i++) {
        int d = qt * 24 + i * 2;
        float2 gv = *(const float2*)(gg + d);
        float2 bv = *(const float2*)(bb + d);
        float ox = (v[2*i]   - mean) * rstd * gv.x + bv.x;
        float oy = (v[2*i+1] - mean) * rstd * gv.y + bv.y;
        if (OUT == 0) {
            *(__half2*)(dst_h + row * PAH + d) = __floats2half2_rn(ox, oy);
        } else {
            *(float2*)(dst_f + row * 96 + d) = make_float2(ox, oy);
        }
    }
}

__global__ void __launch_bounds__(NT, 2)
win_block_kernel(const float* __restrict__ x,
                 const float* __restrict__ ln1_g, const float* __restrict__ ln1_b,
                 const float* __restrict__ qkv_b,
                 const float* __restrict__ out_b,
                 const float* __restrict__ ln2_g, const float* __restrict__ ln2_b,
                 const float* __restrict__ ffn_b1, const float* __restrict__ ffn_b2,
                 const float* __restrict__ pln_g, const float* __restrict__ pln_b,
                 float* __restrict__ out) {
    extern __shared__ char sm[];
    __half* s_qk  = (__half*)(sm + OFF_QK);   // 128 x 200 (Q|K)
    __half* s_v   = (__half*)(sm + OFF_V);    // 128 x 104 (V row-major)
    __half* s_a   = (__half*)(sm + OFF_A);    // 128 x 104
    __half* s_g   = (__half*)(sm + OFF_QK);   // alias (gelu out 128x200)
    float*  s_fin = (float*)(sm + OFF_QK);    // alias (final LN fp32)
    __half* s_h   = (__half*)(sm + OFF_V);    // alias (residual half 128x96)

    const uint32_t uQK = smem_u32(s_qk);
    const uint32_t uV  = smem_u32(s_v);
    const uint32_t uA  = smem_u32(s_a);
    const uint32_t uG  = smem_u32(s_g);

    const int tid = threadIdx.x;
    const int w0  = blockIdx.x * WPC;
    const int b   = blockIdx.y;
    const float* xb = x + (size_t)b * L_SEQ * 96;

    ln128<0, 1>(nullptr, xb, w0, s_a, nullptr, ln1_g, ln1_b, tid);
    __syncthreads();

    gemmM<3, 5>(uA, g_pb4 + PB4_Q, qkv_b, s_qk, PQK, nullptr, s_v, xb, w0, tid);
    __syncthreads();

    attn_mma(uQK, uV, s_a, tid);
    __syncthreads();

    gemmM<1, 2>(uA, g_pb4 + PB4_O, out_b, nullptr, 0, s_h, nullptr, xb, w0, tid);
    __syncthreads();

    ln128<0, 0>(s_h, nullptr, 0, s_a, nullptr, ln2_g, ln2_b, tid);
    __syncthreads();

    gemmM<2, 1>(uA, g_pb4 + PB4_F1, ffn_b1, s_g, PGH, nullptr, nullptr, xb, w0, tid);
    __syncthreads();

    gemmW2(uG, g_pb4 + PB4_W2, ffn_b2, s_h, tid);
    __syncthreads();

    ln128<1, 0>(s_h, nullptr, 0, nullptr, s_fin, pln_g, pln_b, tid);
    __syncthreads();

    int nw = NUM_WIN - w0; if (nw > WPC) nw = WPC;
    const int LP = nw * 8 + 8;
    for (int i = tid; i < LP * 96; i += NT) {
        int lp = i / 96, d = i - lp * 96;
        int pos = w0 * STRIDE + lp;
        size_t oidx = ((size_t)b * L_SEQ + pos) * 96 + d;
        if (lp >= 8 && lp < nw * 8) {
            int wiH = lp >> 3, r = lp & 7;
            float vH = s_fin[(wiH * 16 + r) * 96 + d];
            float vL = s_fin[((wiH - 1) * 16 + r + 8) * 96 + d];
            out[oidx] = (vH + vL) * 0.5f;
        } else if (lp < 8) {
            float invc = (pos < STRIDE) ? 1.0f : 0.5f;
            atomicAdd(out + oidx, s_fin[lp * 96 + d] * invc);
        } else {
            int r = lp - (nw - 1) * 8;
            float invc = (pos >= L_SEQ - STRIDE) ? 1.0f : 0.5f;
            atomicAdd(out + oidx, s_fin[((nw - 1) * 16 + r) * 96 + d] * invc);
        }
    }
}

extern "C" void kernel_launch(void* const* d_in, const int* in_sizes, int n_in,
                              void* d_out, int out_size) {
    const float* x      = (const float*)d_in[0];
    const float* ln1_g  = (const float*)d_in[1];
    const float* ln1_b  = (const float*)d_in[2];
    const float* qkv_w  = (const float*)d_in[3];
    const float* qkv_b  = (const float*)d_in[4];
    const float* out_w  = (const float*)d_in[5];
    const float* out_b  = (const float*)d_in[6];
    const float* ln2_g  = (const float*)d_in[7];
    const float* ln2_b  = (const float*)d_in[8];
    const float* ffn_w1 = (const float*)d_in[9];
    const float* ffn_b1 = (const float*)d_in[10];
    const float* ffn_w2 = (const float*)d_in[11];
    const float* ffn_b2 = (const float*)d_in[12];
    const float* pln_g  = (const float*)d_in[13];
    const float* pln_b  = (const float*)d_in[14];
    float* out = (float*)d_out;

    const int B = in_sizes[0] / (L_SEQ * 96);
    const int nblk = (NUM_WIN + WPC - 1) / WPC;   // 128

    static int attr_set = 0;
    if (!attr_set) {
        cudaFuncSetAttribute(win_block_kernel,
                             cudaFuncAttributeMaxDynamicSharedMemorySize, SMEM_BYTES);
        attr_set = 1;
    }

    prep_kernel<<<(out_size + 255) / 256, 256>>>(qkv_w, out_w, ffn_w1, ffn_w2, out, out_size);

    dim3 grid(nblk, B);
    win_block_kernel<<<grid, NT, SMEM_BYTES>>>(
        x, ln1_g, ln1_b, qkv_b, out_b, ln2_g, ln2_b,
        ffn_b1, ffn_b2, pln_g, pln_b, out);
}